// round 5
// baseline (speedup 1.0000x reference)
#include <cuda_runtime.h>
#include <cuda_bf16.h>
#include <cstdint>
#include <math.h>

#define C_    256
#define HH    30
#define WW    40
#define BB    4
#define TT    4
#define HW_   1200
#define PW    42
#define NP    1344          // 32*42 padded pixels
#define ROWS  1536          // 64 guard + 1344 + 128 guard
#define RBASE 64
#define AROWS 214           // 128 + 2*43
#define SAS   40            // smem k stride in bf16 (32 + 8 pad)

// ---------------- scratch (device globals) ----------------------------------
__device__ __nv_bfloat16 g_Xh [TT*BB*ROWS*C_], g_Xl [TT*BB*ROWS*C_];
__device__ __nv_bfloat16 g_Hh [BB*ROWS*C_],    g_Hl [BB*ROWS*C_];
__device__ __nv_bfloat16 g_XTh[BB*ROWS*C_],    g_XTl[BB*ROWS*C_];
__device__ __nv_bfloat16 g_WAh[2*9*256*C_],    g_WAl[2*9*256*C_];
__device__ __nv_bfloat16 g_WGh[2*9*1024*C_],   g_WGl[2*9*1024*C_];
__device__ float g_att[BB*NP*C_];
__device__ float g_gt [BB*(long)NP*1024];
__device__ float g_cS [BB*NP*C_];
__device__ float g_e  [BB*HW_];
__device__ float g_a  [BB*HW_];

// ---------------- PTX helpers ------------------------------------------------
#define LDSM4(arr, addr) asm volatile( \
    "ldmatrix.sync.aligned.m8n8.x4.shared.b16 {%0,%1,%2,%3}, [%4];" \
    : "=r"((arr)[0]), "=r"((arr)[1]), "=r"((arr)[2]), "=r"((arr)[3]) : "r"(addr))
#define LDSM2(arr, addr) asm volatile( \
    "ldmatrix.sync.aligned.m8n8.x2.shared.b16 {%0,%1}, [%2];" \
    : "=r"((arr)[0]), "=r"((arr)[1]) : "r"(addr))
#define MMA_BF16(d, a, bfr) asm volatile( \
    "mma.sync.aligned.m16n8k16.row.col.f32.bf16.bf16.f32 " \
    "{%0,%1,%2,%3}, {%4,%5,%6,%7}, {%8,%9}, {%0,%1,%2,%3};" \
    : "+f"((d)[0]), "+f"((d)[1]), "+f"((d)[2]), "+f"((d)[3]) \
    : "r"((a)[0]), "r"((a)[1]), "r"((a)[2]), "r"((a)[3]), "r"((bfr)[0]), "r"((bfr)[1]))

__device__ __forceinline__ uint32_t s2u(const void* p) {
    return (uint32_t)__cvta_generic_to_shared(p);
}
__device__ __forceinline__ void splitf(float v, __nv_bfloat16& h, __nv_bfloat16& l) {
    h = __float2bfloat16_rn(v);
    l = __float2bfloat16_rn(v - __bfloat162float(h));
}

// ---------------- activation transpose + split: x NCHW -> [t][b][rows][ci] --
__global__ void xprep_k(const float* __restrict__ x) {
    __shared__ float tile[32][33];
    const int tx = threadIdx.x, ty = threadIdx.y;
    const int p0 = blockIdx.x * 32, ci0 = blockIdx.y * 32;
    const int t = blockIdx.z >> 2, b = blockIdx.z & 3;
    const float* src = x + (((long)b*TT + t)*C_ + ci0) * HW_;
    for (int i = ty; i < 32; i += 8) {
        int p = p0 + tx;
        tile[i][tx] = (p < HW_) ? src[(long)i*HW_ + p] : 0.f;
    }
    __syncthreads();
    __nv_bfloat16* dh = g_Xh + ((long)t*BB + b) * ROWS * C_;
    __nv_bfloat16* dl = g_Xl + ((long)t*BB + b) * ROWS * C_;
    for (int i = ty; i < 32; i += 8) {
        int p = p0 + i;
        if (p >= HW_) continue;
        int q = (p/WW + 1)*PW + (p%WW) + 1;
        float v = tile[tx][i];
        __nv_bfloat16 h, l; splitf(v, h, l);
        long o = ((long)(RBASE + q))*C_ + ci0 + tx;
        dh[o] = h; dl[o] = l;
    }
}

// ---------------- weight transpose + split: HWIO -> [j][t][co][ci] ----------
__global__ void wprep_k(const float* __restrict__ W, __nv_bfloat16* __restrict__ Dh,
                        __nv_bfloat16* __restrict__ Dl, int cout, int jslot) {
    __shared__ float tile[32][33];
    const int tx = threadIdx.x, ty = threadIdx.y;
    const int t = blockIdx.x, co0 = blockIdx.y * 32, ci0 = blockIdx.z * 32;
    for (int i = ty; i < 32; i += 8)
        tile[i][tx] = W[((long)t*C_ + ci0 + i)*cout + co0 + tx];   // tile[ci][co]
    __syncthreads();
    for (int i = ty; i < 32; i += 8) {
        float v = tile[tx][i];                                     // (ci0+tx, co0+i)
        __nv_bfloat16 h, l; splitf(v, h, l);
        long o = (((long)jslot*9 + t)*cout + co0 + i)*C_ + ci0 + tx;
        Dh[o] = h; Dl[o] = l;
    }
}

// ---------------- h0 = c0 = sum_t x -----------------------------------------
__global__ void init_hc_k() {
    int i = blockIdx.x * blockDim.x + threadIdx.x;
    if (i >= BB*HW_*C_) return;
    int ci = i & 255, rest = i >> 8;
    int p = rest % HW_, b = rest / HW_;
    int q = (p/WW + 1)*PW + (p%WW) + 1;
    float s = 0.f;
#pragma unroll
    for (int t = 0; t < TT; t++) {
        long ix = (((long)t*BB + b)*ROWS + RBASE + q)*C_ + ci;
        s += __bfloat162float(g_Xh[ix]) + __bfloat162float(g_Xl[ix]);
    }
    g_cS[((long)b*NP + q)*C_ + ci] = s;
    __nv_bfloat16 h, l; splitf(s, h, l);
    long ho = ((long)b*ROWS + RBASE + q)*C_ + ci;
    g_Hh[ho] = h; g_Hl[ho] = l;
}

// ---------------- dual-input 3x3 conv as 9-tap shifted GEMM (bf16x3 MMA) ----
// D[q, co] = sum_{j,t,ci} A_j[q+delta_t, ci] * W_j[t, ci, co]   (+bias, opt tanh)
template<int COUT, bool DO_TANH>
__global__ __launch_bounds__(256)
void conv_mma_k(const __nv_bfloat16* __restrict__ A1h, const __nv_bfloat16* __restrict__ A1l,
                const __nv_bfloat16* __restrict__ A2h, const __nv_bfloat16* __restrict__ A2l,
                const __nv_bfloat16* __restrict__ Wh,  const __nv_bfloat16* __restrict__ Wl,
                const float* __restrict__ bias1, const float* __restrict__ bias2,
                float* __restrict__ outp)
{
    __shared__ __align__(16) __nv_bfloat16 sA[2][AROWS*SAS];   // hi/lo, 214 rows x 32k
    __shared__ __align__(16) __nv_bfloat16 sB[2][64*SAS];      // hi/lo, 64 co x 32k

    const int tid = threadIdx.x, lane = tid & 31, wid = tid >> 5;
    const int q0  = blockIdx.x * 128;
    const int co0 = blockIdx.y * 64;
    const int b   = blockIdx.z;
    const int wm  = (wid & 1) * 64;        // warp m offset in tile
    const int wn  = (wid >> 1) * 16;       // warp n offset in tile

    float acc[4][2][4];
#pragma unroll
    for (int mt = 0; mt < 4; mt++)
#pragma unroll
        for (int nt = 0; nt < 2; nt++)
#pragma unroll
            for (int k = 0; k < 4; k++) acc[mt][nt][k] = 0.f;

    const int lr = lane & 7, ls = lane >> 3;
    const int arow = ((ls & 1) << 3) + lr;     // ldmatrix A row-within-16
    const int acol = (ls >> 1) << 3;           // ldmatrix A col sel (0/8)
    const int bcol = (ls & 1) << 3;            // ldmatrix B col sel (0/8)

    const long boff = (long)b * (ROWS * C_);

#pragma unroll 1
    for (int j = 0; j < 2; j++) {
        const __nv_bfloat16* Ah = (j ? A2h : A1h) + boff + (long)(RBASE + q0 - 43) * C_;
        const __nv_bfloat16* Al = (j ? A2l : A1l) + boff + (long)(RBASE + q0 - 43) * C_;
        const __nv_bfloat16* Wjh = Wh + (long)j * 9 * COUT * C_;
        const __nv_bfloat16* Wjl = Wl + (long)j * 9 * COUT * C_;
#pragma unroll 1
        for (int kc = 0; kc < 8; kc++) {
            __syncthreads();
            // stage A tile (214 rows x 32 k) hi+lo
            for (int idx = tid; idx < AROWS*8; idx += 256) {
                int r = idx >> 3, s = idx & 7;
                long go = (long)r * C_ + kc*32 + s*4;
                *(uint2*)&sA[0][r*SAS + s*4] = *(const uint2*)(Ah + go);
                *(uint2*)&sA[1][r*SAS + s*4] = *(const uint2*)(Al + go);
            }
#pragma unroll 1
            for (int t = 0; t < 9; t++) {
                __syncthreads();   // prev tap's MMAs done (and A visible on t=0)
                {
                    int idx = tid;
#pragma unroll
                    for (int it = 0; it < 2; it++, idx += 256) {
                        int r = idx >> 3, s = idx & 7;
                        long wo = ((long)t*COUT + co0 + r)*C_ + kc*32 + s*4;
                        *(uint2*)&sB[0][r*SAS + s*4] = *(const uint2*)(Wjh + wo);
                        *(uint2*)&sB[1][r*SAS + s*4] = *(const uint2*)(Wjl + wo);
                    }
                }
                __syncthreads();
                const int dy = t/3 - 1, dx = t%3 - 1;
                const int aoff = (dy*PW + dx + 43) * SAS;
#pragma unroll
                for (int kk = 0; kk < 2; kk++) {
                    const int kcol = kk * 16;
                    uint32_t afh[4][4], afl[4][4];
#pragma unroll
                    for (int mt = 0; mt < 4; mt++) {
                        int rr = aoff + (wm + mt*16 + arow)*SAS + kcol + acol;
                        LDSM4(afh[mt], s2u(&sA[0][rr]));
                        LDSM4(afl[mt], s2u(&sA[1][rr]));
                    }
                    uint32_t bfh[2][2], bfl[2][2];
#pragma unroll
                    for (int nt = 0; nt < 2; nt++) {
                        int rr = (wn + nt*8 + lr)*SAS + kcol + bcol;
                        LDSM2(bfh[nt], s2u(&sB[0][rr]));
                        LDSM2(bfl[nt], s2u(&sB[1][rr]));
                    }
#pragma unroll
                    for (int mt = 0; mt < 4; mt++)
#pragma unroll
                        for (int nt = 0; nt < 2; nt++) {
                            MMA_BF16(acc[mt][nt], afh[mt], bfh[nt]);
                            MMA_BF16(acc[mt][nt], afh[mt], bfl[nt]);
                            MMA_BF16(acc[mt][nt], afl[mt], bfh[nt]);
                        }
                }
            }
        }
    }

    // epilogue
    const int g = lane >> 2, tg = lane & 3;
#pragma unroll
    for (int nt = 0; nt < 2; nt++) {
        int col = co0 + wn + nt*8 + tg*2;
        float b0v = bias1[col]   + bias2[col];
        float b1v = bias1[col+1] + bias2[col+1];
#pragma unroll
        for (int mt = 0; mt < 4; mt++) {
            int r0 = q0 + wm + mt*16 + g;
            float v0 = acc[mt][nt][0] + b0v, v1 = acc[mt][nt][1] + b1v;
            float v2 = acc[mt][nt][2] + b0v, v3 = acc[mt][nt][3] + b1v;
            if (DO_TANH) { v0 = tanhf(v0); v1 = tanhf(v1); v2 = tanhf(v2); v3 = tanhf(v3); }
            if (r0 < NP) {
                float2 w = make_float2(v0, v1);
                *(float2*)&outp[((long)b*NP + r0)*COUT + col] = w;
            }
            if (r0 + 8 < NP) {
                float2 w = make_float2(v2, v3);
                *(float2*)&outp[((long)b*NP + r0 + 8)*COUT + col] = w;
            }
        }
    }
}

// ---------------- e = conv3x3(att, Va), 256 -> 1 ----------------------------
__global__ void econv_k(const float* __restrict__ Va) {
    __shared__ float red[256];
    const int p = blockIdx.x, b = blockIdx.y;
    const int y = p / WW, x = p % WW;
    const int q = (y+1)*PW + (x+1);
    const int ci = threadIdx.x;
    const float* ab = g_att + (long)b*NP*C_;
    float s = 0.f;
#pragma unroll
    for (int t = 0; t < 9; t++) {
        int yy = y + t/3 - 1, xx = x + t%3 - 1;
        if ((unsigned)yy < (unsigned)HH && (unsigned)xx < (unsigned)WW) {
            int dq = q + (t/3 - 1)*PW + (t%3 - 1);
            s += ab[(long)dq*C_ + ci] * Va[t*C_ + ci];
        }
    }
    red[ci] = s; __syncthreads();
    for (int st = 128; st > 0; st >>= 1) {
        if (ci < st) red[ci] += red[ci + st];
        __syncthreads();
    }
    if (ci == 0) g_e[b*HW_ + p] = red[0];
}

// ---------------- softmax over H*W per batch --------------------------------
__global__ void softmax_k() {
    __shared__ float red[256];
    const int b = blockIdx.x;
    const float* eb = g_e + b*HW_;
    float m = -1e30f;
    for (int i = threadIdx.x; i < HW_; i += 256) m = fmaxf(m, eb[i]);
    red[threadIdx.x] = m; __syncthreads();
    for (int s = 128; s > 0; s >>= 1) {
        if (threadIdx.x < s) red[threadIdx.x] = fmaxf(red[threadIdx.x], red[threadIdx.x+s]);
        __syncthreads();
    }
    m = red[0]; __syncthreads();
    float sum = 0.f;
    for (int i = threadIdx.x; i < HW_; i += 256) sum += expf(eb[i] - m);
    red[threadIdx.x] = sum; __syncthreads();
    for (int s = 128; s > 0; s >>= 1) {
        if (threadIdx.x < s) red[threadIdx.x] += red[threadIdx.x+s];
        __syncthreads();
    }
    float inv = 1.f / red[0];
    for (int i = threadIdx.x; i < HW_; i += 256)
        g_a[b*HW_ + i] = expf(eb[i] - m) * inv;
}

// ---------------- x_tilde = x_t * a, split to bf16 hi/lo --------------------
__global__ void xtilde_k(const __nv_bfloat16* __restrict__ Xth,
                         const __nv_bfloat16* __restrict__ Xtl) {
    int i = blockIdx.x * blockDim.x + threadIdx.x;
    if (i >= BB*HW_*C_) return;
    int ci = i & 255, rest = i >> 8;
    int p = rest % HW_, b = rest / HW_;
    int q = (p/WW + 1)*PW + (p%WW) + 1;
    long ix = ((long)b*ROWS + RBASE + q)*C_ + ci;
    float v = __bfloat162float(Xth[ix]) + __bfloat162float(Xtl[ix]);
    v *= g_a[b*HW_ + p];
    __nv_bfloat16 h, l; splitf(v, h, l);
    g_XTh[ix] = h; g_XTl[ix] = l;
}

// ---------------- LSTM pointwise update -------------------------------------
__global__ void lstm_k(float* __restrict__ outp) {   // outp nullptr except last step
    int i = blockIdx.x * blockDim.x + threadIdx.x;
    if (i >= BB*HW_*C_) return;
    int ci = i & 255, rest = i >> 8;
    int p = rest % HW_, b = rest / HW_;
    int q = (p/WW + 1)*PW + (p%WW) + 1;
    long gb = ((long)b*NP + q)*1024 + ci;
    float gi = g_gt[gb], gf = g_gt[gb+256], gcv = g_gt[gb+512], go = g_gt[gb+768];
    long cix = ((long)b*NP + q)*C_ + ci;
    float iv = 1.f / (1.f + expf(-gi));
    float fv = 1.f / (1.f + expf(-gf));
    float ov = 1.f / (1.f + expf(-go));
    float cn = fv * g_cS[cix] + iv * tanhf(gcv);
    float hn = ov * tanhf(cn);
    g_cS[cix] = cn;
    __nv_bfloat16 h, l; splitf(hn, h, l);
    long ho = ((long)b*ROWS + RBASE + q)*C_ + ci;
    g_Hh[ho] = h; g_Hl[ho] = l;
    if (outp) outp[((long)b*C_ + ci)*HW_ + p] = hn;
}

// ---------------------------------------------------------------------------
extern "C" void kernel_launch(void* const* d_in, const int* in_sizes, int n_in,
                              void* d_out, int out_size)
{
    const float* x   = (const float*)d_in[0];
    const float* Wa  = (const float*)d_in[1];
    const float* ba  = (const float*)d_in[2];
    const float* Ua  = (const float*)d_in[3];
    const float* bua = (const float*)d_in[4];
    const float* Va  = (const float*)d_in[5];
    const float* Wx  = (const float*)d_in[6];
    const float* bx  = (const float*)d_in[7];
    const float* Uh  = (const float*)d_in[8];
    const float* bh  = (const float*)d_in[9];
    float* out = (float*)d_out;

    void *pXh, *pXl, *pHh, *pHl, *pXTh, *pXTl, *pWAh, *pWAl, *pWGh, *pWGl, *pAtt, *pG;
    cudaGetSymbolAddress(&pXh,  g_Xh);  cudaGetSymbolAddress(&pXl,  g_Xl);
    cudaGetSymbolAddress(&pHh,  g_Hh);  cudaGetSymbolAddress(&pHl,  g_Hl);
    cudaGetSymbolAddress(&pXTh, g_XTh); cudaGetSymbolAddress(&pXTl, g_XTl);
    cudaGetSymbolAddress(&pWAh, g_WAh); cudaGetSymbolAddress(&pWAl, g_WAl);
    cudaGetSymbolAddress(&pWGh, g_WGh); cudaGetSymbolAddress(&pWGl, g_WGl);
    cudaGetSymbolAddress(&pAtt, g_att); cudaGetSymbolAddress(&pG,   g_gt);

    // zero guard borders (interiors rewritten every call)
    cudaMemsetAsync(pXh,  0, sizeof(__nv_bfloat16)*TT*BB*ROWS*C_);
    cudaMemsetAsync(pXl,  0, sizeof(__nv_bfloat16)*TT*BB*ROWS*C_);
    cudaMemsetAsync(pHh,  0, sizeof(__nv_bfloat16)*BB*ROWS*C_);
    cudaMemsetAsync(pHl,  0, sizeof(__nv_bfloat16)*BB*ROWS*C_);
    cudaMemsetAsync(pXTh, 0, sizeof(__nv_bfloat16)*BB*ROWS*C_);
    cudaMemsetAsync(pXTl, 0, sizeof(__nv_bfloat16)*BB*ROWS*C_);

    // prep: transpose+split activations and weights
    xprep_k<<<dim3(38, 8, 16), dim3(32, 8)>>>(x);
    wprep_k<<<dim3(9,  8, 8), dim3(32, 8)>>>(Wa, (__nv_bfloat16*)pWAh, (__nv_bfloat16*)pWAl, 256,  0);
    wprep_k<<<dim3(9,  8, 8), dim3(32, 8)>>>(Ua, (__nv_bfloat16*)pWAh, (__nv_bfloat16*)pWAl, 256,  1);
    wprep_k<<<dim3(9, 32, 8), dim3(32, 8)>>>(Wx, (__nv_bfloat16*)pWGh, (__nv_bfloat16*)pWGl, 1024, 0);
    wprep_k<<<dim3(9, 32, 8), dim3(32, 8)>>>(Uh, (__nv_bfloat16*)pWGh, (__nv_bfloat16*)pWGl, 1024, 1);

    const int NPT = BB*HW_*C_;            // 1,228,800
    const int NB  = (NPT + 255) / 256;    // 4800
    init_hc_k<<<NB, 256>>>();

    const __nv_bfloat16* Xh = (const __nv_bfloat16*)pXh;
    const __nv_bfloat16* Xl = (const __nv_bfloat16*)pXl;
    const long tstride = (long)BB * ROWS * C_;

    for (int t = 0; t < TT; t++) {
        // att = tanh(conv(h,Wa)+ba + conv(x_t,Ua)+bua)
        conv_mma_k<256, true><<<dim3(11, 4, BB), 256>>>(
            (const __nv_bfloat16*)pHh, (const __nv_bfloat16*)pHl,
            Xh + t*tstride, Xl + t*tstride,
            (const __nv_bfloat16*)pWAh, (const __nv_bfloat16*)pWAl,
            ba, bua, (float*)pAtt);

        econv_k<<<dim3(HW_, BB), 256>>>(Va);
        softmax_k<<<BB, 256>>>();
        xtilde_k<<<NB, 256>>>(Xh + t*tstride, Xl + t*tstride);

        // g = conv(x_tilde,Wx)+bx + conv(h,Uh)+bh
        conv_mma_k<1024, false><<<dim3(11, 16, BB), 256>>>(
            (const __nv_bfloat16*)pXTh, (const __nv_bfloat16*)pXTl,
            (const __nv_bfloat16*)pHh, (const __nv_bfloat16*)pHl,
            (const __nv_bfloat16*)pWGh, (const __nv_bfloat16*)pWGl,
            bx, bh, (float*)pG);

        lstm_k<<<NB, 256>>>((t == TT-1) ? out : (float*)nullptr);
    }
}

// round 9
// speedup vs baseline: 1.0858x; 1.0858x over previous
#include <cuda_runtime.h>
#include <cuda_bf16.h>
#include <cstdint>
#include <math.h>

#define C_    256
#define HH    30
#define WW    40
#define BB    4
#define TT    4
#define HW_   1200
#define PW    42
#define NP    1344          // 32*42 padded pixels
#define ROWS  1536          // 64 guard + 1344 + 128 guard
#define RBASE 64
#define AR    150           // A smem rows: 64 + 2*43
#define AST   72            // smem elem stride (144B: conflict-free for ldmatrix)
#define ASZ   (AR*AST)      // elems per A hi/lo plane (10800)

// ---------------- scratch (device globals) ----------------------------------
__device__ __align__(256) __nv_bfloat16 g_Xh [TT*BB*ROWS*C_], g_Xl [TT*BB*ROWS*C_];
__device__ __align__(256) __nv_bfloat16 g_Hh [BB*ROWS*C_],    g_Hl [BB*ROWS*C_];
__device__ __align__(256) __nv_bfloat16 g_XTh[BB*ROWS*C_],    g_XTl[BB*ROWS*C_];
__device__ __align__(256) __nv_bfloat16 g_WAh[2*9*256*C_],    g_WAl[2*9*256*C_];
__device__ __align__(256) __nv_bfloat16 g_WGh[2*9*1024*C_],   g_WGl[2*9*1024*C_];
__device__ __align__(256) float g_att[(size_t)BB*NP*C_];
__device__ __align__(256) float g_gt [(size_t)BB*NP*1024];
__device__ __align__(256) float g_cS [(size_t)BB*NP*C_];
__device__ float g_e[BB*HW_];
__device__ float g_a[BB*HW_];

// ---------------- PTX helpers ------------------------------------------------
#define LDSM4(arr, addr) asm volatile( \
    "ldmatrix.sync.aligned.m8n8.x4.shared.b16 {%0,%1,%2,%3}, [%4];" \
    : "=r"((arr)[0]), "=r"((arr)[1]), "=r"((arr)[2]), "=r"((arr)[3]) : "r"(addr))
#define MMA_BF16(d, a, bfr) asm volatile( \
    "mma.sync.aligned.m16n8k16.row.col.f32.bf16.bf16.f32 " \
    "{%0,%1,%2,%3}, {%4,%5,%6,%7}, {%8,%9}, {%0,%1,%2,%3};" \
    : "+f"((d)[0]), "+f"((d)[1]), "+f"((d)[2]), "+f"((d)[3]) \
    : "r"((a)[0]), "r"((a)[1]), "r"((a)[2]), "r"((a)[3]), "r"((bfr)[0]), "r"((bfr)[1]))
#define CP16(d_, s_)  asm volatile("cp.async.cg.shared.global [%0], [%1], 16;" :: "r"(d_), "l"(s_))
#define CPCOMMIT()    asm volatile("cp.async.commit_group;" ::: "memory")
#define CPWAIT0()     asm volatile("cp.async.wait_group 0;" ::: "memory")

__device__ __forceinline__ uint32_t s2u(const void* p){ return (uint32_t)__cvta_generic_to_shared(p); }
__device__ __forceinline__ void splitf(float v, __nv_bfloat16& h, __nv_bfloat16& l){
    h = __float2bfloat16_rn(v); l = __float2bfloat16_rn(v - __bfloat162float(h));
}

// ---------------- x NCHW -> channel-last hi/lo [t][b][rows][ci] -------------
__global__ void xprep_k(const float* __restrict__ x){
    __shared__ float tile[32][33];
    const int tx = threadIdx.x, ty = threadIdx.y;
    const int p0 = blockIdx.x*32, ci0 = blockIdx.y*32;
    const int t = blockIdx.z >> 2, b = blockIdx.z & 3;
    const float* src = x + (((size_t)b*TT + t)*C_ + ci0) * HW_;
    for (int i = ty; i < 32; i += 8){
        int p = p0 + tx;
        tile[i][tx] = (p < HW_) ? src[(size_t)i*HW_ + p] : 0.f;
    }
    __syncthreads();
    __nv_bfloat16* dh = g_Xh + ((size_t)t*BB + b)*ROWS*C_;
    __nv_bfloat16* dl = g_Xl + ((size_t)t*BB + b)*ROWS*C_;
    for (int i = ty; i < 32; i += 8){
        int p = p0 + i;
        if (p >= HW_) continue;
        int q = (p/WW + 1)*PW + (p%WW) + 1;
        __nv_bfloat16 h, l; splitf(tile[tx][i], h, l);
        size_t o = ((size_t)(RBASE + q))*C_ + ci0 + tx;
        dh[o] = h; dl[o] = l;
    }
}

// ---------------- weights HWIO -> [j][t][co][ci] hi/lo -----------------------
__global__ void wprep_k(const float* __restrict__ W, __nv_bfloat16* __restrict__ Dh,
                        __nv_bfloat16* __restrict__ Dl, int cout, int jslot){
    __shared__ float tile[32][33];
    const int tx = threadIdx.x, ty = threadIdx.y;
    const int t = blockIdx.x, co0 = blockIdx.y*32, ci0 = blockIdx.z*32;
    for (int i = ty; i < 32; i += 8)
        tile[i][tx] = W[((size_t)t*C_ + ci0 + i)*cout + co0 + tx];
    __syncthreads();
    for (int i = ty; i < 32; i += 8){
        __nv_bfloat16 h, l; splitf(tile[tx][i], h, l);
        size_t o = (((size_t)jslot*9 + t)*cout + co0 + i)*C_ + ci0 + tx;
        Dh[o] = h; Dl[o] = l;
    }
}

// ---------------- h0 = c0 = sum_t x ------------------------------------------
__global__ void init_hc_k(){
    int i = blockIdx.x*blockDim.x + threadIdx.x;
    if (i >= BB*HW_*C_) return;
    int ci = i & 255, rest = i >> 8;
    int p = rest % HW_, b = rest / HW_;
    int q = (p/WW + 1)*PW + (p%WW) + 1;
    float s = 0.f;
#pragma unroll
    for (int t = 0; t < TT; t++){
        size_t ix = (((size_t)t*BB + b)*ROWS + RBASE + q)*C_ + ci;
        s += __bfloat162float(g_Xh[ix]) + __bfloat162float(g_Xl[ix]);
    }
    g_cS[((size_t)(b*NP + q))*C_ + ci] = s;
    __nv_bfloat16 h, l; splitf(s, h, l);
    size_t ho = ((size_t)b*ROWS + RBASE + q)*C_ + ci;
    g_Hh[ho] = h; g_Hl[ho] = l;
}

// ---------------- dual-input 3x3 conv: pipelined HMMA GEMM -------------------
// out[(b*NP+q), co] = sum_{j,t,ci} A_j[q+dlt(t), ci] * W_j[t, ci, co]  (+bias)
// CTA: 64 q-rows x NT co.  A staged per (j, 64-ci chunk) serving all 9 taps.
template<int COUT, int NT, bool DO_TANH>
__global__ __launch_bounds__(256, 2)
void conv_tc_k(const __nv_bfloat16* __restrict__ A1h, const __nv_bfloat16* __restrict__ A1l,
               const __nv_bfloat16* __restrict__ A2h, const __nv_bfloat16* __restrict__ A2l,
               const __nv_bfloat16* __restrict__ Wh,  const __nv_bfloat16* __restrict__ Wl,
               const float* __restrict__ b1, const float* __restrict__ b2,
               float* __restrict__ outp)
{
    constexpr int NF = NT/32;                 // n8-frags per warp
    extern __shared__ __nv_bfloat16 smem[];   // [2*ASZ) A hi/lo | [2*NT*AST) W hi/lo
    const uint32_t sAu = s2u(smem);
    const uint32_t sWu = sAu + 2*ASZ*2;

    const int tid = threadIdx.x, lane = tid & 31, wid = tid >> 5;
    const int q0 = blockIdx.x*64, n0 = blockIdx.y*NT, b = blockIdx.z;
    const int wm = (wid & 1)*32, wn = (wid >> 1)*(NT/4);

    const size_t bo = (size_t)b * ROWS * C_ + (size_t)(RBASE + q0 - 43) * C_;
    const __nv_bfloat16* Abh[2] = { A1h + bo, A2h + bo };
    const __nv_bfloat16* Abl[2] = { A1l + bo, A2l + bo };

    float acc[2][NF][4];
#pragma unroll
    for (int mt = 0; mt < 2; mt++)
#pragma unroll
        for (int nf = 0; nf < NF; nf++)
#pragma unroll
            for (int e = 0; e < 4; e++) acc[mt][nf][e] = 0.f;

    const int lr = lane & 7, ls = lane >> 3;
    const int arow = ((ls & 1) << 3) + lr, acol = (ls >> 1) << 3;
    const int brow = ((ls >> 1) << 3) + lr, bcol = (ls & 1) << 3;

#pragma unroll 1
    for (int j = 0; j < 2; j++){
#pragma unroll 1
        for (int cic = 0; cic < 4; cic++){
            // stage A (hi+lo, 150 rows x 64 ci)
            {
                const __nv_bfloat16* ph = Abh[j] + cic*64;
                const __nv_bfloat16* pl = Abl[j] + cic*64;
                for (int idx = tid; idx < 2*AR*8; idx += 256){
                    int hl = idx >= AR*8; int w = hl ? idx - AR*8 : idx;
                    int r = w >> 3, c = w & 7;
                    CP16(sAu + (hl*ASZ + r*AST + c*8)*2,
                         (hl ? pl : ph) + (size_t)r*C_ + c*8);
                }
                CPCOMMIT();
            }
            // stage W tap 0
            {
                const size_t wo = ((size_t)(j*9 + 0)*COUT + n0)*C_ + cic*64;
                for (int idx = tid; idx < 2*NT*8; idx += 256){
                    int hl = idx >= NT*8; int w = hl ? idx - NT*8 : idx;
                    int r = w >> 3, c = w & 7;
                    CP16(sWu + (hl*NT*AST + r*AST + c*8)*2,
                         (hl ? Wl : Wh) + wo + (size_t)r*C_ + c*8);
                }
                CPCOMMIT();
            }
#pragma unroll 1
            for (int t = 0; t < 9; t++){
                CPWAIT0();
                __syncthreads();
                const int dlt = (t/3 - 1)*PW + (t%3 - 1);
#pragma unroll
                for (int k16 = 0; k16 < 4; k16++){
                    const int kc = k16*16;
                    uint32_t bh[NF][2], bl[NF][2];
#pragma unroll
                    for (int g = 0; g < NF/2; g++){
                        uint32_t tb[4];
                        uint32_t ra = sWu + ((wn + g*16 + brow)*AST + kc + bcol)*2;
                        LDSM4(tb, ra);
                        bh[2*g][0]=tb[0]; bh[2*g][1]=tb[1];
                        bh[2*g+1][0]=tb[2]; bh[2*g+1][1]=tb[3];
                        LDSM4(tb, ra + NT*AST*2);
                        bl[2*g][0]=tb[0]; bl[2*g][1]=tb[1];
                        bl[2*g+1][0]=tb[2]; bl[2*g+1][1]=tb[3];
                    }
#pragma unroll
                    for (int mt = 0; mt < 2; mt++){
                        uint32_t ah[4], al[4];
                        uint32_t ra = sAu + ((43 + dlt + wm + mt*16 + arow)*AST + kc + acol)*2;
                        LDSM4(ah, ra);
                        LDSM4(al, ra + ASZ*2);
#pragma unroll
                        for (int nf = 0; nf < NF; nf++){
                            MMA_BF16(acc[mt][nf], ah, bh[nf]);
                            MMA_BF16(acc[mt][nf], al, bh[nf]);
                            MMA_BF16(acc[mt][nf], ah, bl[nf]);
                        }
                    }
                }
                __syncthreads();
                if (t < 8){   // stage W tap t+1 (single buffer: safe after barrier)
                    const size_t wo = ((size_t)(j*9 + t + 1)*COUT + n0)*C_ + cic*64;
                    for (int idx = tid; idx < 2*NT*8; idx += 256){
                        int hl = idx >= NT*8; int w = hl ? idx - NT*8 : idx;
                        int r = w >> 3, c = w & 7;
                        CP16(sWu + (hl*NT*AST + r*AST + c*8)*2,
                             (hl ? Wl : Wh) + wo + (size_t)r*C_ + c*8);
                    }
                    CPCOMMIT();
                }
            }
        }
    }

    // epilogue: acc -> global [ (b*NP + row)*COUT + col ]
    const int g = lane >> 2, cg = (lane & 3)*2;
#pragma unroll
    for (int nf = 0; nf < NF; nf++){
        int col = n0 + wn + nf*8 + cg;
        float bz0 = __ldg(b1 + col)     + __ldg(b2 + col);
        float bz1 = __ldg(b1 + col + 1) + __ldg(b2 + col + 1);
#pragma unroll
        for (int mt = 0; mt < 2; mt++){
            int row = q0 + wm + mt*16 + g;
            float v0 = acc[mt][nf][0] + bz0, v1 = acc[mt][nf][1] + bz1;
            float v2 = acc[mt][nf][2] + bz0, v3 = acc[mt][nf][3] + bz1;
            if (DO_TANH){ v0 = tanhf(v0); v1 = tanhf(v1); v2 = tanhf(v2); v3 = tanhf(v3); }
            *(float2*)&outp[((size_t)(b*NP + row))*COUT + col]     = make_float2(v0, v1);
            *(float2*)&outp[((size_t)(b*NP + row + 8))*COUT + col] = make_float2(v2, v3);
        }
    }
}

// ---------------- e = conv3x3(att, Va), 256 -> 1 -----------------------------
__global__ void econv_k(const float* __restrict__ Va){
    __shared__ float red[256];
    const int p = blockIdx.x, b = blockIdx.y;
    const int y = p / WW, x = p % WW;
    const int q = (y+1)*PW + (x+1);
    const int ci = threadIdx.x;
    float s = 0.f;
#pragma unroll
    for (int t = 0; t < 9; t++){
        int yy = y + t/3 - 1, xx = x + t%3 - 1;
        if ((unsigned)yy < (unsigned)HH && (unsigned)xx < (unsigned)WW){
            int dq = q + (t/3 - 1)*PW + (t%3 - 1);
            s += g_att[((size_t)(b*NP + dq))*C_ + ci] * Va[t*C_ + ci];
        }
    }
    red[ci] = s; __syncthreads();
    for (int st = 128; st > 0; st >>= 1){
        if (ci < st) red[ci] += red[ci + st];
        __syncthreads();
    }
    if (ci == 0) g_e[b*HW_ + p] = red[0];
}

// ---------------- softmax over H*W per batch ---------------------------------
__global__ void softmax_k(){
    __shared__ float red[256];
    const int b = blockIdx.x;
    const float* eb = g_e + b*HW_;
    float m = -1e30f;
    for (int i = threadIdx.x; i < HW_; i += 256) m = fmaxf(m, eb[i]);
    red[threadIdx.x] = m; __syncthreads();
    for (int s = 128; s > 0; s >>= 1){
        if (threadIdx.x < s) red[threadIdx.x] = fmaxf(red[threadIdx.x], red[threadIdx.x+s]);
        __syncthreads();
    }
    m = red[0]; __syncthreads();
    float sum = 0.f;
    for (int i = threadIdx.x; i < HW_; i += 256) sum += expf(eb[i] - m);
    red[threadIdx.x] = sum; __syncthreads();
    for (int s = 128; s > 0; s >>= 1){
        if (threadIdx.x < s) red[threadIdx.x] += red[threadIdx.x+s];
        __syncthreads();
    }
    float inv = 1.f / red[0];
    for (int i = threadIdx.x; i < HW_; i += 256)
        g_a[b*HW_ + i] = expf(eb[i] - m) * inv;
}

// ---------------- x_tilde = x_t * a, split to bf16 hi/lo ---------------------
__global__ void xtilde_k(const __nv_bfloat16* __restrict__ Xth,
                         const __nv_bfloat16* __restrict__ Xtl){
    int i = blockIdx.x*blockDim.x + threadIdx.x;
    if (i >= BB*HW_*C_) return;
    int ci = i & 255, rest = i >> 8;
    int p = rest % HW_, b = rest / HW_;
    int q = (p/WW + 1)*PW + (p%WW) + 1;
    size_t ix = ((size_t)b*ROWS + RBASE + q)*C_ + ci;
    float v = __bfloat162float(Xth[ix]) + __bfloat162float(Xtl[ix]);
    v *= g_a[b*HW_ + p];
    __nv_bfloat16 h, l; splitf(v, h, l);
    g_XTh[ix] = h; g_XTl[ix] = l;
}

// ---------------- LSTM pointwise update --------------------------------------
__global__ void lstm_k(float* __restrict__ outp){
    int i = blockIdx.x*blockDim.x + threadIdx.x;
    if (i >= BB*HW_*C_) return;
    int ci = i & 255, rest = i >> 8;
    int p = rest % HW_, b = rest / HW_;
    int q = (p/WW + 1)*PW + (p%WW) + 1;
    size_t gb = ((size_t)(b*NP + q))*1024 + ci;
    float gi = g_gt[gb], gf = g_gt[gb+256], gcv = g_gt[gb+512], go = g_gt[gb+768];
    size_t cx = ((size_t)(b*NP + q))*C_ + ci;
    float iv = 1.f/(1.f + expf(-gi));
    float fv = 1.f/(1.f + expf(-gf));
    float ov = 1.f/(1.f + expf(-go));
    float cn = fv*g_cS[cx] + iv*tanhf(gcv);
    float hn = ov*tanhf(cn);
    g_cS[cx] = cn;
    __nv_bfloat16 h, l; splitf(hn, h, l);
    size_t ho = ((size_t)b*ROWS + RBASE + q)*C_ + ci;
    g_Hh[ho] = h; g_Hl[ho] = l;
    if (outp) outp[((size_t)(b*C_ + ci))*HW_ + p] = hn;
}

// -----------------------------------------------------------------------------
extern "C" void kernel_launch(void* const* d_in, const int* in_sizes, int n_in,
                              void* d_out, int out_size)
{
    const float* x   = (const float*)d_in[0];
    const float* Wa  = (const float*)d_in[1];
    const float* ba  = (const float*)d_in[2];
    const float* Ua  = (const float*)d_in[3];
    const float* bua = (const float*)d_in[4];
    const float* Va  = (const float*)d_in[5];
    const float* Wx  = (const float*)d_in[6];
    const float* bx  = (const float*)d_in[7];
    const float* Uh  = (const float*)d_in[8];
    const float* bh  = (const float*)d_in[9];
    float* out = (float*)d_out;

    void *pXh, *pXl, *pHh, *pHl, *pXTh, *pXTl, *pWAh, *pWAl, *pWGh, *pWGl, *pAtt, *pG;
    cudaGetSymbolAddress(&pXh, g_Xh);   cudaGetSymbolAddress(&pXl, g_Xl);
    cudaGetSymbolAddress(&pHh, g_Hh);   cudaGetSymbolAddress(&pHl, g_Hl);
    cudaGetSymbolAddress(&pXTh, g_XTh); cudaGetSymbolAddress(&pXTl, g_XTl);
    cudaGetSymbolAddress(&pWAh, g_WAh); cudaGetSymbolAddress(&pWAl, g_WAl);
    cudaGetSymbolAddress(&pWGh, g_WGh); cudaGetSymbolAddress(&pWGl, g_WGl);
    cudaGetSymbolAddress(&pAtt, g_att); cudaGetSymbolAddress(&pG, g_gt);

    const int SMEM_ATT  = (2*ASZ + 2*64*AST)  * 2;   // 61,632 B
    const int SMEM_GATE = (2*ASZ + 2*128*AST) * 2;   // 80,064 B
    cudaFuncSetAttribute(conv_tc_k<256,  64,  true >, cudaFuncAttributeMaxDynamicSharedMemorySize, SMEM_ATT);
    cudaFuncSetAttribute(conv_tc_k<1024, 128, false>, cudaFuncAttributeMaxDynamicSharedMemorySize, SMEM_GATE);

    // zero guard borders (interiors rewritten every call)
    cudaMemsetAsync(pXh,  0, sizeof(__nv_bfloat16)*TT*BB*ROWS*C_);
    cudaMemsetAsync(pXl,  0, sizeof(__nv_bfloat16)*TT*BB*ROWS*C_);
    cudaMemsetAsync(pHh,  0, sizeof(__nv_bfloat16)*BB*ROWS*C_);
    cudaMemsetAsync(pHl,  0, sizeof(__nv_bfloat16)*BB*ROWS*C_);
    cudaMemsetAsync(pXTh, 0, sizeof(__nv_bfloat16)*BB*ROWS*C_);
    cudaMemsetAsync(pXTl, 0, sizeof(__nv_bfloat16)*BB*ROWS*C_);

    xprep_k<<<dim3(38, 8, 16), dim3(32, 8)>>>(x);
    wprep_k<<<dim3(9,  8, 8), dim3(32, 8)>>>(Wa, (__nv_bfloat16*)pWAh, (__nv_bfloat16*)pWAl, 256,  0);
    wprep_k<<<dim3(9,  8, 8), dim3(32, 8)>>>(Ua, (__nv_bfloat16*)pWAh, (__nv_bfloat16*)pWAl, 256,  1);
    wprep_k<<<dim3(9, 32, 8), dim3(32, 8)>>>(Wx, (__nv_bfloat16*)pWGh, (__nv_bfloat16*)pWGl, 1024, 0);
    wprep_k<<<dim3(9, 32, 8), dim3(32, 8)>>>(Uh, (__nv_bfloat16*)pWGh, (__nv_bfloat16*)pWGl, 1024, 1);

    const int NPT = BB*HW_*C_, NB = (NPT + 255)/256;
    init_hc_k<<<NB, 256>>>();

    const __nv_bfloat16* Xh = (const __nv_bfloat16*)pXh;
    const __nv_bfloat16* Xl = (const __nv_bfloat16*)pXl;
    const size_t ts = (size_t)BB*ROWS*C_;

    for (int t = 0; t < TT; t++){
        // att = tanh(conv(h,Wa)+ba + conv(x_t,Ua)+bua)
        conv_tc_k<256, 64, true><<<dim3(21, 4, BB), 256, SMEM_ATT>>>(
            (const __nv_bfloat16*)pHh, (const __nv_bfloat16*)pHl,
            Xh + t*ts, Xl + t*ts,
            (const __nv_bfloat16*)pWAh, (const __nv_bfloat16*)pWAl,
            ba, bua, (float*)pAtt);

        econv_k<<<dim3(HW_, BB), 256>>>(Va);
        softmax_k<<<BB, 256>>>();
        xtilde_k<<<NB, 256>>>(Xh + t*ts, Xl + t*ts);

        // g = conv(x_tilde,Wx)+bx + conv(h,Uh)+bh
        conv_tc_k<1024, 128, false><<<dim3(21, 8, BB), 256, SMEM_GATE>>>(
            (const __nv_bfloat16*)pXTh, (const __nv_bfloat16*)pXTl,
            (const __nv_bfloat16*)pHh, (const __nv_bfloat16*)pHl,
            (const __nv_bfloat16*)pWGh, (const __nv_bfloat16*)pWGl,
            bx, bh, (float*)pG);

        lstm_k<<<NB, 256>>>((t == TT-1) ? out : (float*)nullptr);
    }
}

// round 10
// speedup vs baseline: 2.5919x; 2.3870x over previous
#include <cuda_runtime.h>
#include <cuda_bf16.h>
#include <cstdint>
#include <math.h>

#define C_    256
#define HH    30
#define WW    40
#define BB    4
#define TT    4
#define HW_   1200
#define PW2   42            // padded width (W+2)
#define NP    1344          // 32*42 padded pixels per image
#define KW    512           // GEMM K (2 inputs * 256 ci)
#define MR    1216          // GEMM M rows (19*64 >= 1200 tiles)
#define TLS   1200          // total output tiles: 4 batches * 15*20

// ---------------- scratch (device globals) ----------------------------------
__device__ __align__(256) float g_x32 [(size_t)TT*BB*NP*C_];
__device__ __align__(256) float g_h32 [(size_t)BB*NP*C_];
__device__ __align__(256) float g_xt32[(size_t)BB*NP*C_];
__device__ __align__(256) float g_cS  [(size_t)BB*NP*C_];
__device__ __align__(256) float g_att [(size_t)BB*NP*C_];
__device__ __align__(256) float g_gt  [(size_t)BB*NP*1024];
__device__ float g_e[BB*HW_], g_a[BB*HW_];
__device__ __align__(256) __nv_bfloat16 g_Uh [(size_t)16*MR*KW],   g_Ul [(size_t)16*MR*KW];
__device__ __align__(256) __nv_bfloat16 g_WGh[(size_t)16*1024*KW], g_WGl[(size_t)16*1024*KW];
__device__ __align__(256) __nv_bfloat16 g_WAh[(size_t)16*256*KW],  g_WAl[(size_t)16*256*KW];
__device__ __align__(256) float g_M [(size_t)16*MR*1024];
__device__ __align__(256) float g_Ma[(size_t)16*MR*256];

// ---------------- PTX helpers ------------------------------------------------
#define LDSM4(arr, addr) asm volatile( \
    "ldmatrix.sync.aligned.m8n8.x4.shared.b16 {%0,%1,%2,%3}, [%4];" \
    : "=r"((arr)[0]), "=r"((arr)[1]), "=r"((arr)[2]), "=r"((arr)[3]) : "r"(addr))
#define MMA_BF16(d, a, bfr) asm volatile( \
    "mma.sync.aligned.m16n8k16.row.col.f32.bf16.bf16.f32 " \
    "{%0,%1,%2,%3}, {%4,%5,%6,%7}, {%8,%9}, {%0,%1,%2,%3};" \
    : "+f"((d)[0]), "+f"((d)[1]), "+f"((d)[2]), "+f"((d)[3]) \
    : "r"((a)[0]), "r"((a)[1]), "r"((a)[2]), "r"((a)[3]), "r"((bfr)[0]), "r"((bfr)[1]))
#define CP16(d_, s_)  asm volatile("cp.async.cg.shared.global [%0], [%1], 16;" :: "r"(d_), "l"(s_))
#define CPCOMMIT()    asm volatile("cp.async.commit_group;" ::: "memory")
#define CPWAIT1()     asm volatile("cp.async.wait_group 1;" ::: "memory")
#define CPWAIT0()     asm volatile("cp.async.wait_group 0;" ::: "memory")

__device__ __forceinline__ uint32_t s2u(const void* p){ return (uint32_t)__cvta_generic_to_shared(p); }
__device__ __forceinline__ void splitf(float v, __nv_bfloat16& h, __nv_bfloat16& l){
    h = __float2bfloat16_rn(v); l = __float2bfloat16_rn(v - __bfloat162float(h));
}

// ---------------- x NCHW -> fp32 padded channel-last [t*BB+b][NP][C] --------
__global__ void xprep_k(const float* __restrict__ x){
    __shared__ float tile[32][33];
    const int tx = threadIdx.x, ty = threadIdx.y;
    const int p0 = blockIdx.x*32, ci0 = blockIdx.y*32;
    const int t = blockIdx.z >> 2, b = blockIdx.z & 3;
    const float* src = x + (((size_t)b*TT + t)*C_ + ci0) * HW_;
    for (int i = ty; i < 32; i += 8){
        int p = p0 + tx;
        tile[i][tx] = (p < HW_) ? src[(size_t)i*HW_ + p] : 0.f;
    }
    __syncthreads();
    float* dst = g_x32 + ((size_t)t*BB + b)*NP*C_;
    for (int i = ty; i < 32; i += 8){
        int p = p0 + i;
        if (p >= HW_) continue;
        int q = (p/WW + 1)*PW2 + (p%WW) + 1;
        dst[(size_t)q*C_ + ci0 + tx] = tile[tx][i];
    }
}

// ---------------- Winograd weight transform: HWIO -> Wt[uv][co][j*256+ci] ---
__global__ void wtr_k(const float* __restrict__ W, int cout, int jslot,
                      __nv_bfloat16* __restrict__ Dh, __nv_bfloat16* __restrict__ Dl){
    const int co = blockIdx.x, ci = threadIdx.x;
    float g[3][3];
#pragma unroll
    for (int k = 0; k < 9; k++)
        g[k/3][k%3] = W[((size_t)k*C_ + ci)*cout + co];
    float r[4][3];
#pragma unroll
    for (int c = 0; c < 3; c++){
        r[0][c] = g[0][c];
        r[1][c] = 0.5f*(g[0][c] + g[1][c] + g[2][c]);
        r[2][c] = 0.5f*(g[0][c] - g[1][c] + g[2][c]);
        r[3][c] = g[2][c];
    }
#pragma unroll
    for (int rr = 0; rr < 4; rr++){
        float a = r[rr][0], b = r[rr][1], c = r[rr][2];
        float w4[4] = { a, 0.5f*(a+b+c), 0.5f*(a-b+c), c };
#pragma unroll
        for (int cc = 0; cc < 4; cc++){
            __nv_bfloat16 h, l; splitf(w4[cc], h, l);
            size_t o = ((size_t)(rr*4+cc)*cout + co)*KW + jslot*256 + ci;
            Dh[o] = h; Dl[o] = l;
        }
    }
}

// ---------------- Winograd input transform -> U[uv][tile][j*256+ci] ---------
__global__ void itr_k(const float* __restrict__ src, int jslot){
    const int tt = blockIdx.x, ci = threadIdx.x;
    const int b = tt/300, rr = tt%300, ty = rr/20, tx = rr%20;
    const float* sp = src + ((size_t)b*NP + 2*ty*PW2 + 2*tx)*C_ + ci;
    float d[4][4];
#pragma unroll
    for (int r = 0; r < 4; r++)
#pragma unroll
        for (int c = 0; c < 4; c++)
            d[r][c] = sp[(size_t)(r*PW2 + c)*C_];
    float t[4][4];
#pragma unroll
    for (int c = 0; c < 4; c++){
        t[0][c] = d[0][c] - d[2][c];
        t[1][c] = d[1][c] + d[2][c];
        t[2][c] = d[2][c] - d[1][c];
        t[3][c] = d[1][c] - d[3][c];
    }
#pragma unroll
    for (int r = 0; r < 4; r++){
        float z0 = t[r][0] - t[r][2];
        float z1 = t[r][1] + t[r][2];
        float z2 = t[r][2] - t[r][1];
        float z3 = t[r][1] - t[r][3];
        float zz[4] = { z0, z1, z2, z3 };
#pragma unroll
        for (int c = 0; c < 4; c++){
            __nv_bfloat16 h, l; splitf(zz[c], h, l);
            size_t o = ((size_t)(r*4+c)*MR + tt)*KW + jslot*256 + ci;
            g_Uh[o] = h; g_Ul[o] = l;
        }
    }
}

// ---------------- GEMM: M[uv][row][co] = U[uv] . Wt[uv]^T  (bf16x3 HMMA) ----
template<int COUT>
__global__ __launch_bounds__(256, 2)
void gemm_k(const __nv_bfloat16* __restrict__ Wh_g, const __nv_bfloat16* __restrict__ Wl_g,
            float* __restrict__ Mout)
{
    extern __shared__ char smem[];
    const uint32_t sb0 = s2u(smem);
    const int tid = threadIdx.x, lane = tid & 31, wid = tid >> 5;
    const int m0 = blockIdx.x*64, n0 = blockIdx.y*128, uv = blockIdx.z;
    const size_t Ab = ((size_t)uv*MR + m0)*KW;
    const size_t Bb = ((size_t)uv*COUT + n0)*KW;

    auto stage = [&](int kc, int s){
        const uint32_t sb = sb0 + s*55296;
#pragma unroll
        for (int u = 0; u < 12; u++){
            int idx = tid + (u << 8);
            const __nv_bfloat16* src; uint32_t dst;
            if (idx < 1024){
                int hl = idx >> 9, w = idx & 511, r = w >> 3, c = w & 7;
                src = (hl ? g_Ul : g_Uh) + Ab + (size_t)r*KW + kc*64 + c*8;
                dst = sb + hl*9216 + (r*72 + c*8)*2;
            } else {
                int w = idx - 1024; int hl = w >> 10; w &= 1023;
                int r = w >> 3, c = w & 7;
                src = (hl ? Wl_g : Wh_g) + Bb + (size_t)r*KW + kc*64 + c*8;
                dst = sb + 18432 + hl*18432 + (r*72 + c*8)*2;
            }
            CP16(dst, src);
        }
        CPCOMMIT();
    };

    float acc[2][4][4];
#pragma unroll
    for (int mt = 0; mt < 2; mt++)
#pragma unroll
        for (int nf = 0; nf < 4; nf++)
#pragma unroll
            for (int e = 0; e < 4; e++) acc[mt][nf][e] = 0.f;

    const int lr = lane & 7, ls = lane >> 3;
    const int arow = ((ls & 1) << 3) + lr, acol = (ls >> 1) << 3;
    const int brow = ((ls >> 1) << 3) + lr, bcol = (ls & 1) << 3;
    const int wm = (wid & 1)*32, wn = (wid >> 1)*32;

    stage(0, 0);
#pragma unroll 1
    for (int kc = 0; kc < 8; kc++){
        if (kc < 7){ stage(kc+1, (kc+1) & 1); CPWAIT1(); } else CPWAIT0();
        __syncthreads();
        const uint32_t sA = sb0 + (kc & 1)*55296;
        const uint32_t sB = sA + 18432;
#pragma unroll
        for (int k16 = 0; k16 < 4; k16++){
            const int kcc = k16*16;
            uint32_t bh[4][2], bl[4][2];
#pragma unroll
            for (int g = 0; g < 2; g++){
                uint32_t tb[4];
                uint32_t ra = sB + ((wn + g*16 + brow)*72 + kcc + bcol)*2;
                LDSM4(tb, ra);
                bh[2*g][0]=tb[0]; bh[2*g][1]=tb[1]; bh[2*g+1][0]=tb[2]; bh[2*g+1][1]=tb[3];
                LDSM4(tb, ra + 18432);
                bl[2*g][0]=tb[0]; bl[2*g][1]=tb[1]; bl[2*g+1][0]=tb[2]; bl[2*g+1][1]=tb[3];
            }
#pragma unroll
            for (int mt = 0; mt < 2; mt++){
                uint32_t ah[4], al[4];
                uint32_t ra = sA + ((wm + mt*16 + arow)*72 + kcc + acol)*2;
                LDSM4(ah, ra);
                LDSM4(al, ra + 9216);
#pragma unroll
                for (int nf = 0; nf < 4; nf++){
                    MMA_BF16(acc[mt][nf], ah, bh[nf]);
                    MMA_BF16(acc[mt][nf], al, bh[nf]);
                    MMA_BF16(acc[mt][nf], ah, bl[nf]);
                }
            }
        }
        __syncthreads();
    }

    const int g2 = lane >> 2, cg = (lane & 3)*2;
#pragma unroll
    for (int nf = 0; nf < 4; nf++){
        int col = n0 + wn + nf*8 + cg;
#pragma unroll
        for (int mt = 0; mt < 2; mt++){
            int row = m0 + wm + mt*16 + g2;
            *(float2*)&Mout[((size_t)uv*MR + row)*COUT + col]     = make_float2(acc[mt][nf][0], acc[mt][nf][1]);
            *(float2*)&Mout[((size_t)uv*MR + row + 8)*COUT + col] = make_float2(acc[mt][nf][2], acc[mt][nf][3]);
        }
    }
}

// ---------------- Winograd output transform + bias (+opt tanh) --------------
template<int COUT, bool DO_TANH>
__global__ void otr_k(const float* __restrict__ Msrc, const float* __restrict__ b1,
                      const float* __restrict__ b2, float* __restrict__ dst){
    const int tt = blockIdx.x;
    const int co = blockIdx.y*256 + threadIdx.x;
    const int b = tt/300, rr = tt%300, ty = rr/20, tx = rr%20;
    float m[4][4];
#pragma unroll
    for (int uv = 0; uv < 16; uv++)
        m[uv>>2][uv&3] = Msrc[((size_t)uv*MR + tt)*COUT + co];
    float u0[4], u1[4];
#pragma unroll
    for (int c = 0; c < 4; c++){
        u0[c] = m[0][c] + m[1][c] + m[2][c];
        u1[c] = m[1][c] - m[2][c] - m[3][c];
    }
    float y[2][2];
    y[0][0] = u0[0] + u0[1] + u0[2];  y[0][1] = u0[1] - u0[2] - u0[3];
    y[1][0] = u1[0] + u1[1] + u1[2];  y[1][1] = u1[1] - u1[2] - u1[3];
    const float bz = __ldg(b1 + co) + __ldg(b2 + co);
#pragma unroll
    for (int oy = 0; oy < 2; oy++)
#pragma unroll
        for (int ox = 0; ox < 2; ox++){
            float v = y[oy][ox] + bz;
            if (DO_TANH) v = tanhf(v);
            int pix = (2*ty + oy + 1)*PW2 + (2*tx + ox + 1);
            dst[((size_t)(b*NP + pix))*COUT + co] = v;
        }
}

// ---------------- h0 = c0 = sum_t x ------------------------------------------
__global__ void init_hc_k(){
    int i = blockIdx.x*blockDim.x + threadIdx.x;
    if (i >= BB*HW_*C_) return;
    int ci = i & 255, rest = i >> 8;
    int p = rest % HW_, b = rest / HW_;
    int q = (p/WW + 1)*PW2 + (p%WW) + 1;
    float s = 0.f;
#pragma unroll
    for (int t = 0; t < TT; t++)
        s += g_x32[(((size_t)t*BB + b)*NP + q)*C_ + ci];
    size_t o = ((size_t)b*NP + q)*C_ + ci;
    g_cS[o] = s;
    g_h32[o] = s;
}

// ---------------- e = conv3x3(att, Va), 256 -> 1 -----------------------------
__global__ void econv_k(const float* __restrict__ Va){
    __shared__ float red[256];
    const int p = blockIdx.x, b = blockIdx.y;
    const int y = p / WW, x = p % WW;
    const int q = (y+1)*PW2 + (x+1);
    const int ci = threadIdx.x;
    float s = 0.f;
#pragma unroll
    for (int t = 0; t < 9; t++){
        int yy = y + t/3 - 1, xx = x + t%3 - 1;
        if ((unsigned)yy < (unsigned)HH && (unsigned)xx < (unsigned)WW){
            int dq = q + (t/3 - 1)*PW2 + (t%3 - 1);
            s += g_att[((size_t)(b*NP + dq))*C_ + ci] * Va[t*C_ + ci];
        }
    }
    red[ci] = s; __syncthreads();
    for (int st = 128; st > 0; st >>= 1){
        if (ci < st) red[ci] += red[ci + st];
        __syncthreads();
    }
    if (ci == 0) g_e[b*HW_ + p] = red[0];
}

// ---------------- softmax over H*W per batch ---------------------------------
__global__ void softmax_k(){
    __shared__ float red[256];
    const int b = blockIdx.x;
    const float* eb = g_e + b*HW_;
    float m = -1e30f;
    for (int i = threadIdx.x; i < HW_; i += 256) m = fmaxf(m, eb[i]);
    red[threadIdx.x] = m; __syncthreads();
    for (int s = 128; s > 0; s >>= 1){
        if (threadIdx.x < s) red[threadIdx.x] = fmaxf(red[threadIdx.x], red[threadIdx.x+s]);
        __syncthreads();
    }
    m = red[0]; __syncthreads();
    float sum = 0.f;
    for (int i = threadIdx.x; i < HW_; i += 256) sum += expf(eb[i] - m);
    red[threadIdx.x] = sum; __syncthreads();
    for (int s = 128; s > 0; s >>= 1){
        if (threadIdx.x < s) red[threadIdx.x] += red[threadIdx.x+s];
        __syncthreads();
    }
    float inv = 1.f / red[0];
    for (int i = threadIdx.x; i < HW_; i += 256)
        g_a[b*HW_ + i] = expf(eb[i] - m) * inv;
}

// ---------------- x_tilde = x_t * a ------------------------------------------
__global__ void xtilde_k(const float* __restrict__ xt_slab){
    int i = blockIdx.x*blockDim.x + threadIdx.x;
    if (i >= BB*HW_*C_) return;
    int ci = i & 255, rest = i >> 8;
    int p = rest % HW_, b = rest / HW_;
    int q = (p/WW + 1)*PW2 + (p%WW) + 1;
    size_t ix = ((size_t)b*NP + q)*C_ + ci;
    g_xt32[ix] = xt_slab[ix] * g_a[b*HW_ + p];
}

// ---------------- LSTM pointwise update --------------------------------------
__global__ void lstm_k(float* __restrict__ outp){
    int i = blockIdx.x*blockDim.x + threadIdx.x;
    if (i >= BB*HW_*C_) return;
    int ci = i & 255, rest = i >> 8;
    int p = rest % HW_, b = rest / HW_;
    int q = (p/WW + 1)*PW2 + (p%WW) + 1;
    size_t gb = ((size_t)(b*NP + q))*1024 + ci;
    float gi = g_gt[gb], gf = g_gt[gb+256], gcv = g_gt[gb+512], go = g_gt[gb+768];
    size_t cx = ((size_t)(b*NP + q))*C_ + ci;
    float iv = 1.f/(1.f + expf(-gi));
    float fv = 1.f/(1.f + expf(-gf));
    float ov = 1.f/(1.f + expf(-go));
    float cn = fv*g_cS[cx] + iv*tanhf(gcv);
    float hn = ov*tanhf(cn);
    g_cS[cx] = cn;
    g_h32[cx] = hn;
    if (outp) outp[((size_t)(b*C_ + ci))*HW_ + p] = hn;
}

// -----------------------------------------------------------------------------
extern "C" void kernel_launch(void* const* d_in, const int* in_sizes, int n_in,
                              void* d_out, int out_size)
{
    const float* x   = (const float*)d_in[0];
    const float* Wa  = (const float*)d_in[1];
    const float* ba  = (const float*)d_in[2];
    const float* Ua  = (const float*)d_in[3];
    const float* bua = (const float*)d_in[4];
    const float* Va  = (const float*)d_in[5];
    const float* Wx  = (const float*)d_in[6];
    const float* bx  = (const float*)d_in[7];
    const float* Uh  = (const float*)d_in[8];
    const float* bh  = (const float*)d_in[9];
    float* out = (float*)d_out;

    void *pX, *pH, *pXT, *pWAh, *pWAl, *pWGh, *pWGl, *pM, *pMa, *pAtt, *pG;
    cudaGetSymbolAddress(&pX,  g_x32);
    cudaGetSymbolAddress(&pH,  g_h32);
    cudaGetSymbolAddress(&pXT, g_xt32);
    cudaGetSymbolAddress(&pWAh, g_WAh); cudaGetSymbolAddress(&pWAl, g_WAl);
    cudaGetSymbolAddress(&pWGh, g_WGh); cudaGetSymbolAddress(&pWGl, g_WGl);
    cudaGetSymbolAddress(&pM,  g_M);    cudaGetSymbolAddress(&pMa, g_Ma);
    cudaGetSymbolAddress(&pAtt, g_att); cudaGetSymbolAddress(&pG,  g_gt);

    const int SMEM = 2*55296;   // 110,592 B (double-buffered stage)
    cudaFuncSetAttribute(gemm_k<256>,  cudaFuncAttributeMaxDynamicSharedMemorySize, SMEM);
    cudaFuncSetAttribute(gemm_k<1024>, cudaFuncAttributeMaxDynamicSharedMemorySize, SMEM);

    // zero padded borders (interiors rewritten each call)
    cudaMemsetAsync(pX,  0, sizeof(float)*(size_t)TT*BB*NP*C_);
    cudaMemsetAsync(pH,  0, sizeof(float)*(size_t)BB*NP*C_);
    cudaMemsetAsync(pXT, 0, sizeof(float)*(size_t)BB*NP*C_);

    xprep_k<<<dim3(38, 8, 16), dim3(32, 8)>>>(x);
    wtr_k<<<256,  256>>>(Wa, 256,  0, (__nv_bfloat16*)pWAh, (__nv_bfloat16*)pWAl);
    wtr_k<<<256,  256>>>(Ua, 256,  1, (__nv_bfloat16*)pWAh, (__nv_bfloat16*)pWAl);
    wtr_k<<<1024, 256>>>(Uh, 1024, 0, (__nv_bfloat16*)pWGh, (__nv_bfloat16*)pWGl);
    wtr_k<<<1024, 256>>>(Wx, 1024, 1, (__nv_bfloat16*)pWGh, (__nv_bfloat16*)pWGl);

    const int NPT = BB*HW_*C_, NB = (NPT + 255)/256;
    init_hc_k<<<NB, 256>>>();

    const float* x32 = (const float*)pX;
    const size_t ts = (size_t)BB*NP*C_;

    for (int t = 0; t < TT; t++){
        // attention: att = tanh(conv(h,Wa)+ba + conv(x_t,Ua)+bua)
        itr_k<<<TLS, 256>>>((const float*)pH, 0);
        itr_k<<<TLS, 256>>>(x32 + t*ts, 1);
        gemm_k<256><<<dim3(19, 2, 16), 256, SMEM>>>(
            (const __nv_bfloat16*)pWAh, (const __nv_bfloat16*)pWAl, (float*)pMa);
        otr_k<256, true><<<dim3(TLS, 1), 256>>>((const float*)pMa, ba, bua, (float*)pAtt);

        econv_k<<<dim3(HW_, BB), 256>>>(Va);
        softmax_k<<<BB, 256>>>();
        xtilde_k<<<NB, 256>>>(x32 + t*ts);

        // gates: g = conv(x_tilde,Wx)+bx + conv(h,Uh)+bh
        itr_k<<<TLS, 256>>>((const float*)pXT, 1);   // overwrite j=1 slot with x_tilde
        gemm_k<1024><<<dim3(19, 8, 16), 256, SMEM>>>(
            (const __nv_bfloat16*)pWGh, (const __nv_bfloat16*)pWGl, (float*)pM);
        otr_k<1024, false><<<dim3(TLS, 4), 256>>>((const float*)pM, bx, bh, (float*)pG);

        lstm_k<<<NB, 256>>>((t == TT-1) ? out : (float*)nullptr);
    }
}

// round 11
// speedup vs baseline: 3.4678x; 1.3380x over previous
#include <cuda_runtime.h>
#include <cuda_bf16.h>
#include <cstdint>
#include <math.h>

#define C_    256
#define HH    30
#define WW    40
#define BB    4
#define TT    4
#define HW_   1200
#define PW2   42            // padded width (1 + 40 + 1)
#define PH2   34            // padded height (1 + 30 + 3)
#define NP    1428          // PH2*PW2 padded pixels per image
#define KW    512           // GEMM K (2 inputs * 256 ci)
#define MR    320           // GEMM M rows: 4 batches * 80 tiles (8x10 of 4x4)
#define UV    36            // 6x6 Winograd components
#define TLS   320           // total tiles

// ---------------- scratch (device globals) ----------------------------------
__device__ __align__(256) float g_x32 [(size_t)TT*BB*NP*C_];
__device__ __align__(256) float g_h32 [(size_t)BB*NP*C_];
__device__ __align__(256) float g_xt32[(size_t)BB*NP*C_];
__device__ __align__(256) float g_cS  [(size_t)BB*NP*C_];
__device__ __align__(256) float g_att [(size_t)BB*NP*C_];
__device__ __align__(256) float g_gt  [(size_t)BB*NP*1024];
__device__ float g_e[BB*HW_], g_a[BB*HW_];
__device__ __align__(256) __nv_bfloat16 g_Uh [(size_t)UV*MR*KW],   g_Ul [(size_t)UV*MR*KW];
__device__ __align__(256) __nv_bfloat16 g_WGh[(size_t)UV*1024*KW], g_WGl[(size_t)UV*1024*KW];
__device__ __align__(256) __nv_bfloat16 g_WAh[(size_t)UV*256*KW],  g_WAl[(size_t)UV*256*KW];
__device__ __align__(256) float g_M [(size_t)UV*MR*1024];
__device__ __align__(256) float g_Ma[(size_t)UV*MR*256];

// ---------------- PTX helpers ------------------------------------------------
#define LDSM4(arr, addr) asm volatile( \
    "ldmatrix.sync.aligned.m8n8.x4.shared.b16 {%0,%1,%2,%3}, [%4];" \
    : "=r"((arr)[0]), "=r"((arr)[1]), "=r"((arr)[2]), "=r"((arr)[3]) : "r"(addr))
#define MMA_BF16(d, a, bfr) asm volatile( \
    "mma.sync.aligned.m16n8k16.row.col.f32.bf16.bf16.f32 " \
    "{%0,%1,%2,%3}, {%4,%5,%6,%7}, {%8,%9}, {%0,%1,%2,%3};" \
    : "+f"((d)[0]), "+f"((d)[1]), "+f"((d)[2]), "+f"((d)[3]) \
    : "r"((a)[0]), "r"((a)[1]), "r"((a)[2]), "r"((a)[3]), "r"((bfr)[0]), "r"((bfr)[1]))
#define CP16(d_, s_)  asm volatile("cp.async.cg.shared.global [%0], [%1], 16;" :: "r"(d_), "l"(s_))
#define CPCOMMIT()    asm volatile("cp.async.commit_group;" ::: "memory")
#define CPWAIT1()     asm volatile("cp.async.wait_group 1;" ::: "memory")
#define CPWAIT0()     asm volatile("cp.async.wait_group 0;" ::: "memory")

__device__ __forceinline__ uint32_t s2u(const void* p){ return (uint32_t)__cvta_generic_to_shared(p); }
__device__ __forceinline__ void splitf(float v, __nv_bfloat16& h, __nv_bfloat16& l){
    h = __float2bfloat16_rn(v); l = __float2bfloat16_rn(v - __bfloat162float(h));
}

// ---------------- x NCHW -> fp32 padded channel-last ------------------------
__global__ void xprep_k(const float* __restrict__ x){
    __shared__ float tile[32][33];
    const int tx = threadIdx.x, ty = threadIdx.y;
    const int p0 = blockIdx.x*32, ci0 = blockIdx.y*32;
    const int t = blockIdx.z >> 2, b = blockIdx.z & 3;
    const float* src = x + (((size_t)b*TT + t)*C_ + ci0) * HW_;
    for (int i = ty; i < 32; i += 8){
        int p = p0 + tx;
        tile[i][tx] = (p < HW_) ? src[(size_t)i*HW_ + p] : 0.f;
    }
    __syncthreads();
    float* dst = g_x32 + ((size_t)t*BB + b)*NP*C_;
    for (int i = ty; i < 32; i += 8){
        int p = p0 + i;
        if (p >= HW_) continue;
        int q = (p/WW + 1)*PW2 + (p%WW) + 1;
        dst[(size_t)q*C_ + ci0 + tx] = tile[tx][i];
    }
}

// ---------------- F(4,3) weight transform: HWIO -> Wt[uv][co][j*256+ci] -----
__global__ void wtr_k(const float* __restrict__ W, int cout, int jslot,
                      __nv_bfloat16* __restrict__ Dh, __nv_bfloat16* __restrict__ Dl){
    const int co = blockIdx.x, ci = threadIdx.x;
    const float S6 = 1.f/6.f, S24 = 1.f/24.f;
    float g[3][3];
#pragma unroll
    for (int k = 0; k < 9; k++)
        g[k/3][k%3] = W[((size_t)k*C_ + ci)*cout + co];
    float u[6][3];
#pragma unroll
    for (int c = 0; c < 3; c++){
        float a = g[0][c], b = g[1][c], cc = g[2][c];
        u[0][c] = 0.25f*a;
        u[1][c] = -S6*(a + b + cc);
        u[2][c] = -S6*(a - b + cc);
        u[3][c] = S24*(a + 2.f*b + 4.f*cc);
        u[4][c] = S24*(a - 2.f*b + 4.f*cc);
        u[5][c] = cc;
    }
#pragma unroll
    for (int i = 0; i < 6; i++){
        float a = u[i][0], b = u[i][1], cc = u[i][2];
        float w[6] = { 0.25f*a, -S6*(a + b + cc), -S6*(a - b + cc),
                       S24*(a + 2.f*b + 4.f*cc), S24*(a - 2.f*b + 4.f*cc), cc };
#pragma unroll
        for (int j = 0; j < 6; j++){
            __nv_bfloat16 h, l; splitf(w[j], h, l);
            size_t o = ((size_t)(i*6+j)*cout + co)*KW + jslot*256 + ci;
            Dh[o] = h; Dl[o] = l;
        }
    }
}

// ---------------- F(4,3) input transform -> U[uv][tile][j*256+ci] -----------
__global__ void itr_k(const float* __restrict__ src, int jslot){
    const int tt = blockIdx.x, ci = threadIdx.x;    // grid = 320
    const int b = tt/80, rr = tt%80, ty = rr/10, tx = rr%10;
    const float* sp = src + ((size_t)b*NP + 4*ty*PW2 + 4*tx)*C_ + ci;
    float t[6][6];
#pragma unroll
    for (int c = 0; c < 6; c++){
        float d0 = sp[(size_t)(0*PW2 + c)*C_];
        float d1 = sp[(size_t)(1*PW2 + c)*C_];
        float d2 = sp[(size_t)(2*PW2 + c)*C_];
        float d3 = sp[(size_t)(3*PW2 + c)*C_];
        float d4 = sp[(size_t)(4*PW2 + c)*C_];
        float d5 = sp[(size_t)(5*PW2 + c)*C_];
        t[0][c] = 4.f*d0 - 5.f*d2 + d4;
        t[1][c] = -4.f*d1 - 4.f*d2 + d3 + d4;
        t[2][c] =  4.f*d1 - 4.f*d2 - d3 + d4;
        t[3][c] = -2.f*d1 - d2 + 2.f*d3 + d4;
        t[4][c] =  2.f*d1 - d2 - 2.f*d3 + d4;
        t[5][c] =  4.f*d1 - 5.f*d3 + d5;
    }
#pragma unroll
    for (int r = 0; r < 6; r++){
        float v0 = t[r][0], v1 = t[r][1], v2 = t[r][2], v3 = t[r][3], v4 = t[r][4], v5 = t[r][5];
        float w[6] = { 4.f*v0 - 5.f*v2 + v4,
                       -4.f*v1 - 4.f*v2 + v3 + v4,
                        4.f*v1 - 4.f*v2 - v3 + v4,
                       -2.f*v1 - v2 + 2.f*v3 + v4,
                        2.f*v1 - v2 - 2.f*v3 + v4,
                        4.f*v1 - 5.f*v3 + v5 };
#pragma unroll
        for (int j = 0; j < 6; j++){
            __nv_bfloat16 h, l; splitf(w[j], h, l);
            size_t o = ((size_t)(r*6+j)*MR + tt)*KW + jslot*256 + ci;
            g_Uh[o] = h; g_Ul[o] = l;
        }
    }
}

// ---------------- GEMM: M[uv][row][co] = U[uv] . Wt[uv]^T  (bf16x3 HMMA) ----
template<int COUT>
__global__ __launch_bounds__(256, 2)
void gemm_k(const __nv_bfloat16* __restrict__ Wh_g, const __nv_bfloat16* __restrict__ Wl_g,
            float* __restrict__ Mout)
{
    extern __shared__ char smem[];
    const uint32_t sb0 = s2u(smem);
    const int tid = threadIdx.x, lane = tid & 31, wid = tid >> 5;
    const int m0 = blockIdx.x*64, n0 = blockIdx.y*128, uv = blockIdx.z;
    const size_t Ab = ((size_t)uv*MR + m0)*KW;
    const size_t Bb = ((size_t)uv*COUT + n0)*KW;

    auto stage = [&](int kc, int s){
        const uint32_t sb = sb0 + s*55296;
#pragma unroll
        for (int u = 0; u < 12; u++){
            int idx = tid + (u << 8);
            const __nv_bfloat16* src; uint32_t dst;
            if (idx < 1024){
                int hl = idx >> 9, w = idx & 511, r = w >> 3, c = w & 7;
                src = (hl ? g_Ul : g_Uh) + Ab + (size_t)r*KW + kc*64 + c*8;
                dst = sb + hl*9216 + (r*72 + c*8)*2;
            } else {
                int w = idx - 1024; int hl = w >> 10; w &= 1023;
                int r = w >> 3, c = w & 7;
                src = (hl ? Wl_g : Wh_g) + Bb + (size_t)r*KW + kc*64 + c*8;
                dst = sb + 18432 + hl*18432 + (r*72 + c*8)*2;
            }
            CP16(dst, src);
        }
        CPCOMMIT();
    };

    float acc[2][4][4];
#pragma unroll
    for (int mt = 0; mt < 2; mt++)
#pragma unroll
        for (int nf = 0; nf < 4; nf++)
#pragma unroll
            for (int e = 0; e < 4; e++) acc[mt][nf][e] = 0.f;

    const int lr = lane & 7, ls = lane >> 3;
    const int arow = ((ls & 1) << 3) + lr, acol = (ls >> 1) << 3;
    const int brow = ((ls >> 1) << 3) + lr, bcol = (ls & 1) << 3;
    const int wm = (wid & 1)*32, wn = (wid >> 1)*32;

    stage(0, 0);
#pragma unroll 1
    for (int kc = 0; kc < 8; kc++){
        if (kc < 7){ stage(kc+1, (kc+1) & 1); CPWAIT1(); } else CPWAIT0();
        __syncthreads();
        const uint32_t sA = sb0 + (kc & 1)*55296;
        const uint32_t sB = sA + 18432;
#pragma unroll
        for (int k16 = 0; k16 < 4; k16++){
            const int kcc = k16*16;
            uint32_t bh[4][2], bl[4][2];
#pragma unroll
            for (int g = 0; g < 2; g++){
                uint32_t tb[4];
                uint32_t ra = sB + ((wn + g*16 + brow)*72 + kcc + bcol)*2;
                LDSM4(tb, ra);
                bh[2*g][0]=tb[0]; bh[2*g][1]=tb[1]; bh[2*g+1][0]=tb[2]; bh[2*g+1][1]=tb[3];
                LDSM4(tb, ra + 18432);
                bl[2*g][0]=tb[0]; bl[2*g][1]=tb[1]; bl[2*g+1][0]=tb[2]; bl[2*g+1][1]=tb[3];
            }
#pragma unroll
            for (int mt = 0; mt < 2; mt++){
                uint32_t ah[4], al[4];
                uint32_t ra = sA + ((wm + mt*16 + arow)*72 + kcc + acol)*2;
                LDSM4(ah, ra);
                LDSM4(al, ra + 9216);
#pragma unroll
                for (int nf = 0; nf < 4; nf++){
                    MMA_BF16(acc[mt][nf], ah, bh[nf]);
                    MMA_BF16(acc[mt][nf], al, bh[nf]);
                    MMA_BF16(acc[mt][nf], ah, bl[nf]);
                }
            }
        }
        __syncthreads();
    }

    const int g2 = lane >> 2, cg = (lane & 3)*2;
#pragma unroll
    for (int nf = 0; nf < 4; nf++){
        int col = n0 + wn + nf*8 + cg;
#pragma unroll
        for (int mt = 0; mt < 2; mt++){
            int row = m0 + wm + mt*16 + g2;
            *(float2*)&Mout[((size_t)uv*MR + row)*COUT + col]     = make_float2(acc[mt][nf][0], acc[mt][nf][1]);
            *(float2*)&Mout[((size_t)uv*MR + row + 8)*COUT + col] = make_float2(acc[mt][nf][2], acc[mt][nf][3]);
        }
    }
}

// ---------------- F(4,3) output transform + bias (+opt tanh) ----------------
template<int COUT, bool DO_TANH>
__global__ void otr_k(const float* __restrict__ Msrc, const float* __restrict__ b1,
                      const float* __restrict__ b2, float* __restrict__ dst){
    const int tt = blockIdx.x;
    const int co = blockIdx.y*256 + threadIdx.x;
    const int b = tt/80, rr = tt%80, ty = rr/10, tx = rr%10;
    float m[6][6];
#pragma unroll
    for (int uv = 0; uv < UV; uv++)
        m[uv/6][uv%6] = Msrc[((size_t)uv*MR + tt)*COUT + co];
    float z[4][6];
#pragma unroll
    for (int c = 0; c < 6; c++){
        float m1 = m[1][c], m2 = m[2][c], m3 = m[3][c], m4 = m[4][c];
        z[0][c] = m[0][c] + m1 + m2 + m3 + m4;
        z[1][c] = m1 - m2 + 2.f*(m3 - m4);
        z[2][c] = m1 + m2 + 4.f*(m3 + m4);
        z[3][c] = m1 - m2 + 8.f*(m3 - m4) + m[5][c];
    }
    const float bz = __ldg(b1 + co) + __ldg(b2 + co);
#pragma unroll
    for (int r = 0; r < 4; r++){
        int oy = 4*ty + r;
        if (oy >= HH) continue;
        float v1 = z[r][1], v2 = z[r][2], v3 = z[r][3], v4 = z[r][4];
        float y[4] = { z[r][0] + v1 + v2 + v3 + v4,
                       v1 - v2 + 2.f*(v3 - v4),
                       v1 + v2 + 4.f*(v3 + v4),
                       v1 - v2 + 8.f*(v3 - v4) + z[r][5] };
#pragma unroll
        for (int cxx = 0; cxx < 4; cxx++){
            float v = y[cxx] + bz;
            if (DO_TANH) v = tanhf(v);
            int pix = (oy + 1)*PW2 + (4*tx + cxx + 1);
            dst[((size_t)(b*NP + pix))*COUT + co] = v;
        }
    }
}

// ---------------- h0 = c0 = sum_t x ------------------------------------------
__global__ void init_hc_k(){
    int i = blockIdx.x*blockDim.x + threadIdx.x;
    if (i >= BB*HW_*C_) return;
    int ci = i & 255, rest = i >> 8;
    int p = rest % HW_, b = rest / HW_;
    int q = (p/WW + 1)*PW2 + (p%WW) + 1;
    float s = 0.f;
#pragma unroll
    for (int t = 0; t < TT; t++)
        s += g_x32[(((size_t)t*BB + b)*NP + q)*C_ + ci];
    size_t o = ((size_t)b*NP + q)*C_ + ci;
    g_cS[o] = s;
    g_h32[o] = s;
}

// ---------------- e = conv3x3(att, Va), 256 -> 1 -----------------------------
__global__ void econv_k(const float* __restrict__ Va){
    __shared__ float red[256];
    const int p = blockIdx.x, b = blockIdx.y;
    const int y = p / WW, x = p % WW;
    const int q = (y+1)*PW2 + (x+1);
    const int ci = threadIdx.x;
    float s = 0.f;
#pragma unroll
    for (int t = 0; t < 9; t++){
        int yy = y + t/3 - 1, xx = x + t%3 - 1;
        if ((unsigned)yy < (unsigned)HH && (unsigned)xx < (unsigned)WW){
            int dq = q + (t/3 - 1)*PW2 + (t%3 - 1);
            s += g_att[((size_t)(b*NP + dq))*C_ + ci] * Va[t*C_ + ci];
        }
    }
    red[ci] = s; __syncthreads();
    for (int st = 128; st > 0; st >>= 1){
        if (ci < st) red[ci] += red[ci + st];
        __syncthreads();
    }
    if (ci == 0) g_e[b*HW_ + p] = red[0];
}

// ---------------- softmax over H*W per batch ---------------------------------
__global__ void softmax_k(){
    __shared__ float red[256];
    const int b = blockIdx.x;
    const float* eb = g_e + b*HW_;
    float m = -1e30f;
    for (int i = threadIdx.x; i < HW_; i += 256) m = fmaxf(m, eb[i]);
    red[threadIdx.x] = m; __syncthreads();
    for (int s = 128; s > 0; s >>= 1){
        if (threadIdx.x < s) red[threadIdx.x] = fmaxf(red[threadIdx.x], red[threadIdx.x+s]);
        __syncthreads();
    }
    m = red[0]; __syncthreads();
    float sum = 0.f;
    for (int i = threadIdx.x; i < HW_; i += 256) sum += expf(eb[i] - m);
    red[threadIdx.x] = sum; __syncthreads();
    for (int s = 128; s > 0; s >>= 1){
        if (threadIdx.x < s) red[threadIdx.x] += red[threadIdx.x+s];
        __syncthreads();
    }
    float inv = 1.f / red[0];
    for (int i = threadIdx.x; i < HW_; i += 256)
        g_a[b*HW_ + i] = expf(eb[i] - m) * inv;
}

// ---------------- x_tilde = x_t * a ------------------------------------------
__global__ void xtilde_k(const float* __restrict__ xt_slab){
    int i = blockIdx.x*blockDim.x + threadIdx.x;
    if (i >= BB*HW_*C_) return;
    int ci = i & 255, rest = i >> 8;
    int p = rest % HW_, b = rest / HW_;
    int q = (p/WW + 1)*PW2 + (p%WW) + 1;
    size_t ix = ((size_t)b*NP + q)*C_ + ci;
    g_xt32[ix] = xt_slab[ix] * g_a[b*HW_ + p];
}

// ---------------- LSTM pointwise update --------------------------------------
__global__ void lstm_k(float* __restrict__ outp){
    int i = blockIdx.x*blockDim.x + threadIdx.x;
    if (i >= BB*HW_*C_) return;
    int ci = i & 255, rest = i >> 8;
    int p = rest % HW_, b = rest / HW_;
    int q = (p/WW + 1)*PW2 + (p%WW) + 1;
    size_t gb = ((size_t)(b*NP + q))*1024 + ci;
    float gi = g_gt[gb], gf = g_gt[gb+256], gcv = g_gt[gb+512], go = g_gt[gb+768];
    size_t cx = ((size_t)(b*NP + q))*C_ + ci;
    float iv = 1.f/(1.f + expf(-gi));
    float fv = 1.f/(1.f + expf(-gf));
    float ov = 1.f/(1.f + expf(-go));
    float cn = fv*g_cS[cx] + iv*tanhf(gcv);
    float hn = ov*tanhf(cn);
    g_cS[cx] = cn;
    g_h32[cx] = hn;
    if (outp) outp[((size_t)(b*C_ + ci))*HW_ + p] = hn;
}

// -----------------------------------------------------------------------------
extern "C" void kernel_launch(void* const* d_in, const int* in_sizes, int n_in,
                              void* d_out, int out_size)
{
    const float* x   = (const float*)d_in[0];
    const float* Wa  = (const float*)d_in[1];
    const float* ba  = (const float*)d_in[2];
    const float* Ua  = (const float*)d_in[3];
    const float* bua = (const float*)d_in[4];
    const float* Va  = (const float*)d_in[5];
    const float* Wx  = (const float*)d_in[6];
    const float* bx  = (const float*)d_in[7];
    const float* Uh  = (const float*)d_in[8];
    const float* bh  = (const float*)d_in[9];
    float* out = (float*)d_out;

    void *pX, *pH, *pXT, *pWAh, *pWAl, *pWGh, *pWGl, *pM, *pMa, *pAtt, *pG;
    cudaGetSymbolAddress(&pX,  g_x32);
    cudaGetSymbolAddress(&pH,  g_h32);
    cudaGetSymbolAddress(&pXT, g_xt32);
    cudaGetSymbolAddress(&pWAh, g_WAh); cudaGetSymbolAddress(&pWAl, g_WAl);
    cudaGetSymbolAddress(&pWGh, g_WGh); cudaGetSymbolAddress(&pWGl, g_WGl);
    cudaGetSymbolAddress(&pM,  g_M);    cudaGetSymbolAddress(&pMa, g_Ma);
    cudaGetSymbolAddress(&pAtt, g_att); cudaGetSymbolAddress(&pG,  g_gt);

    const int SMEM = 2*55296;   // 110,592 B double-buffered stage
    cudaFuncSetAttribute(gemm_k<256>,  cudaFuncAttributeMaxDynamicSharedMemorySize, SMEM);
    cudaFuncSetAttribute(gemm_k<1024>, cudaFuncAttributeMaxDynamicSharedMemorySize, SMEM);

    // zero padded borders (interiors rewritten each call)
    cudaMemsetAsync(pX,  0, sizeof(float)*(size_t)TT*BB*NP*C_);
    cudaMemsetAsync(pH,  0, sizeof(float)*(size_t)BB*NP*C_);
    cudaMemsetAsync(pXT, 0, sizeof(float)*(size_t)BB*NP*C_);

    xprep_k<<<dim3(38, 8, 16), dim3(32, 8)>>>(x);
    wtr_k<<<256,  256>>>(Wa, 256,  0, (__nv_bfloat16*)pWAh, (__nv_bfloat16*)pWAl);
    wtr_k<<<256,  256>>>(Ua, 256,  1, (__nv_bfloat16*)pWAh, (__nv_bfloat16*)pWAl);
    wtr_k<<<1024, 256>>>(Uh, 1024, 0, (__nv_bfloat16*)pWGh, (__nv_bfloat16*)pWGl);
    wtr_k<<<1024, 256>>>(Wx, 1024, 1, (__nv_bfloat16*)pWGh, (__nv_bfloat16*)pWGl);

    const int NPT = BB*HW_*C_, NB = (NPT + 255)/256;
    init_hc_k<<<NB, 256>>>();

    const float* x32 = (const float*)pX;
    const size_t ts = (size_t)BB*NP*C_;

    for (int t = 0; t < TT; t++){
        // attention: att = tanh(conv(h,Wa)+ba + conv(x_t,Ua)+bua)
        itr_k<<<TLS, 256>>>((const float*)pH, 0);
        itr_k<<<TLS, 256>>>(x32 + t*ts, 1);
        gemm_k<256><<<dim3(5, 2, UV), 256, SMEM>>>(
            (const __nv_bfloat16*)pWAh, (const __nv_bfloat16*)pWAl, (float*)pMa);
        otr_k<256, true><<<dim3(TLS, 1), 256>>>((const float*)pMa, ba, bua, (float*)pAtt);

        econv_k<<<dim3(HW_, BB), 256>>>(Va);
        softmax_k<<<BB, 256>>>();
        xtilde_k<<<NB, 256>>>(x32 + t*ts);

        // gates: g = conv(x_tilde,Wx)+bx + conv(h,Uh)+bh
        itr_k<<<TLS, 256>>>((const float*)pXT, 1);   // overwrite j=1 slot with x_tilde
        gemm_k<1024><<<dim3(5, 8, UV), 256, SMEM>>>(
            (const __nv_bfloat16*)pWGh, (const __nv_bfloat16*)pWGl, (float*)pM);
        otr_k<1024, false><<<dim3(TLS, 4), 256>>>((const float*)pM, bx, bh, (float*)pG);

        lstm_k<<<NB, 256>>>((t == TT-1) ? out : (float*)nullptr);
    }
}